// round 12
// baseline (speedup 1.0000x reference)
#include <cuda_runtime.h>
#include <cstdint>

#define HW 1024
#define BATCH 8

__device__ float g_cat [BATCH * 1024 * HW];
__device__ float g_z   [BATCH * 256  * HW];
__device__ float g_qkv [BATCH * 768  * HW];    // raw fp32 qkv conv output
__device__ float g_qkvp[BATCH * 768  * HW];    // packed tf32 bits (K has bias)
__device__ float g_att [BATCH * 256  * HW];
__device__ float g_w3  [2 * 9 * 256 * 256];    // [i][t][co][ci]
__device__ float g_part[9 * BATCH * 256 * HW]; // conv3 per-tap partials

// ---------------------------------------------------------------------------
__device__ __forceinline__ uint32_t f2tf(float x) {
    uint32_t r;
    asm("cvt.rna.tf32.f32 %0, %1;" : "=r"(r) : "f"(x));
    return r;
}

__device__ __forceinline__ void mma8(float c[4],
    uint32_t a0, uint32_t a1, uint32_t a2, uint32_t a3,
    uint32_t b0, uint32_t b1)
{
    asm volatile(
        "mma.sync.aligned.m16n8k8.row.col.f32.tf32.tf32.f32 "
        "{%0,%1,%2,%3}, {%4,%5,%6,%7}, {%8,%9}, {%0,%1,%2,%3};"
        : "+f"(c[0]), "+f"(c[1]), "+f"(c[2]), "+f"(c[3])
        : "r"(a0), "r"(a1), "r"(a2), "r"(a3), "r"(b0), "r"(b1));
}

#define AST 36
#define BST 136

// ---------------------------------------------------------------------------
__global__ void reorder_w3_kernel(const float* __restrict__ w, float* __restrict__ o)
{
    int idx = blockIdx.x * 256 + threadIdx.x;
    if (idx >= 2 * 9 * 65536) return;
    int i  = idx / (9 * 65536);
    int r  = idx % (9 * 65536);
    int t  = r / 65536;
    int rc = r % 65536;
    int co = rc >> 8, ci = rc & 255;
    o[idx] = w[((long)(i * 256 + co) * 256 + ci) * 9 + t];
}

// ---------------------------------------------------------------------------
__device__ __forceinline__ void mma_chunk(
    const uint32_t* __restrict__ As, const uint32_t* __restrict__ Bs,
    int wm, int wn, int lane, float acc[4][4][4])
{
    #pragma unroll
    for (int ks = 0; ks < 4; ks++) {
        uint32_t a[4][4], bb[4][2];
        int ar = wm * 64 + (lane >> 2);
        int ac = ks * 8 + (lane & 3);
        #pragma unroll
        for (int mt = 0; mt < 4; mt++) {
            int r = ar + mt * 16;
            a[mt][0] = As[r * AST + ac];
            a[mt][1] = As[(r + 8) * AST + ac];
            a[mt][2] = As[r * AST + ac + 4];
            a[mt][3] = As[(r + 8) * AST + ac + 4];
        }
        int br = ks * 8 + (lane & 3);
        int bc = wn * 32 + (lane >> 2);
        #pragma unroll
        for (int nt = 0; nt < 4; nt++) {
            bb[nt][0] = Bs[br * BST + bc + nt * 8];
            bb[nt][1] = Bs[(br + 4) * BST + bc + nt * 8];
        }
        #pragma unroll
        for (int mt = 0; mt < 4; mt++)
            #pragma unroll
            for (int nt = 0; nt < 4; nt++)
                mma8(acc[mt][nt], a[mt][0], a[mt][1], a[mt][2], a[mt][3],
                     bb[nt][0], bb[nt][1]);
    }
}

// ---------------------------------------------------------------------------
// tf32 GEMM for 1x1 convs (exact R8 version).
// flags: 1=BN, 2=SiLU, 4=residual.
// ---------------------------------------------------------------------------
__global__ __launch_bounds__(256) void gemm_tf32_kernel(
    const float* __restrict__ X, const float* __restrict__ W,
    const float* __restrict__ bn, const float* __restrict__ res,
    float* __restrict__ out,
    int Cin, int Cout, long xbS, long obS, long rbS, int flags)
{
    __shared__ uint32_t As[128 * AST];
    __shared__ uint32_t Bs[32 * BST];

    const int b   = blockIdx.z;
    const int p0  = blockIdx.x * 128;
    const int co0 = blockIdx.y * 128;
    const int tid = threadIdx.x;
    const int lane = tid & 31, wid = tid >> 5;
    const int wm = wid >> 2, wn = wid & 3;

    const float* Xb = X + (long)b * xbS;

    float acc[4][4][4];
    #pragma unroll
    for (int mt = 0; mt < 4; mt++)
        #pragma unroll
        for (int nt = 0; nt < 4; nt++)
            #pragma unroll
            for (int e = 0; e < 4; e++) acc[mt][nt][e] = 0.f;

    for (int k0 = 0; k0 < Cin; k0 += 32) {
        #pragma unroll
        for (int it = 0; it < 4; it++) {
            int r = (tid >> 3) + it * 32;
            int c = (tid & 7) * 4;
            float4 v = *(const float4*)&W[(long)(co0 + r) * Cin + k0 + c];
            As[r * AST + c + 0] = f2tf(v.x);
            As[r * AST + c + 1] = f2tf(v.y);
            As[r * AST + c + 2] = f2tf(v.z);
            As[r * AST + c + 3] = f2tf(v.w);
        }
        #pragma unroll
        for (int it = 0; it < 4; it++) {
            int kk = (tid >> 5) + it * 8;
            int pp = lane * 4;
            float4 v = *(const float4*)&Xb[(long)(k0 + kk) * HW + p0 + pp];
            Bs[kk * BST + pp + 0] = f2tf(v.x);
            Bs[kk * BST + pp + 1] = f2tf(v.y);
            Bs[kk * BST + pp + 2] = f2tf(v.z);
            Bs[kk * BST + pp + 3] = f2tf(v.w);
        }
        __syncthreads();
        mma_chunk(As, Bs, wm, wn, lane, acc);
        __syncthreads();
    }

    #pragma unroll
    for (int mt = 0; mt < 4; mt++) {
        int r0 = co0 + wm * 64 + mt * 16 + (lane >> 2);
        int r1 = r0 + 8;
        float s0 = 1.f, c0 = 0.f, s1 = 1.f, c1 = 0.f;
        if (flags & 1) {
            float g0 = bn[r0], b0v = bn[Cout + r0], m0 = bn[2*Cout + r0], v0 = bn[3*Cout + r0];
            s0 = g0 * rsqrtf(v0 + 1e-3f); c0 = b0v - m0 * s0;
            float g1 = bn[r1], b1v = bn[Cout + r1], m1 = bn[2*Cout + r1], v1 = bn[3*Cout + r1];
            s1 = g1 * rsqrtf(v1 + 1e-3f); c1 = b1v - m1 * s1;
        }
        #pragma unroll
        for (int nt = 0; nt < 4; nt++) {
            int col = p0 + wn * 32 + nt * 8 + 2 * (lane & 3);
            float v00 = acc[mt][nt][0] * s0 + c0;
            float v01 = acc[mt][nt][1] * s0 + c0;
            float v10 = acc[mt][nt][2] * s1 + c1;
            float v11 = acc[mt][nt][3] * s1 + c1;
            if (flags & 2) {
                v00 = v00 / (1.f + __expf(-v00));
                v01 = v01 / (1.f + __expf(-v01));
                v10 = v10 / (1.f + __expf(-v10));
                v11 = v11 / (1.f + __expf(-v11));
            }
            if (flags & 4) {
                const float* rb = res + (long)b * rbS;
                v00 += rb[(long)r0 * HW + col];
                v01 += rb[(long)r0 * HW + col + 1];
                v10 += rb[(long)r1 * HW + col];
                v11 += rb[(long)r1 * HW + col + 1];
            }
            float* ob = out + (long)b * obS;
            *(float2*)&ob[(long)r0 * HW + col] = make_float2(v00, v01);
            *(float2*)&ob[(long)r1 * HW + col] = make_float2(v10, v11);
        }
    }
}

// ---------------------------------------------------------------------------
// Tap-split tf32 3x3 conv: ONE tap per block (9-way split), K-depth 256 =
// 8 chunks. grid (8, 2*9, BATCH) = 1152 blocks -> ~97% wave fill.
// Partials layout: g_part[tap][b][co][p].
// ---------------------------------------------------------------------------
__global__ __launch_bounds__(256) void conv3_part_kernel(
    const float* __restrict__ X, const float* __restrict__ Wt,
    float* __restrict__ part_out, long xbS)
{
    __shared__ uint32_t As[128 * AST];
    __shared__ uint32_t Bs[32 * BST];

    const int b    = blockIdx.z;
    const int p0   = blockIdx.x * 128;
    const int tap  = blockIdx.y >> 1;
    const int co0  = (blockIdx.y & 1) * 128;
    const int tid  = threadIdx.x;
    const int lane = tid & 31, wid = tid >> 5;
    const int wm = wid >> 2, wn = wid & 3;

    const float* Xb = X + (long)b * xbS;
    const int dy = tap / 3 - 1, dx = tap % 3 - 1;
    const float* Wtt = Wt + tap * 65536;

    float acc[4][4][4];
    #pragma unroll
    for (int mt = 0; mt < 4; mt++)
        #pragma unroll
        for (int nt = 0; nt < 4; nt++)
            #pragma unroll
            for (int e = 0; e < 4; e++) acc[mt][nt][e] = 0.f;

    for (int c = 0; c < 8; c++) {
        const int kc = c * 32;

        #pragma unroll
        for (int it = 0; it < 4; it++) {
            int r = (tid >> 3) + it * 32;
            int cc = (tid & 7) * 4;
            float4 v = *(const float4*)&Wtt[(long)(co0 + r) * 256 + kc + cc];
            As[r * AST + cc + 0] = f2tf(v.x);
            As[r * AST + cc + 1] = f2tf(v.y);
            As[r * AST + cc + 2] = f2tf(v.z);
            As[r * AST + cc + 3] = f2tf(v.w);
        }
        #pragma unroll
        for (int e = tid; e < 4096; e += 256) {
            int kk = e >> 7, p = e & 127;
            int pix = p0 + p;
            int row = (pix >> 5) + dy;
            int col = (pix & 31) + dx;
            float xv = 0.f;
            if ((unsigned)row < 32u && (unsigned)col < 32u)
                xv = Xb[(long)(kc + kk) * HW + row * 32 + col];
            Bs[kk * BST + p] = f2tf(xv);
        }
        __syncthreads();
        mma_chunk(As, Bs, wm, wn, lane, acc);
        __syncthreads();
    }

    float* ob = part_out + ((long)tap * BATCH + b) * 256 * HW;
    #pragma unroll
    for (int mt = 0; mt < 4; mt++) {
        int r0 = co0 + wm * 64 + mt * 16 + (lane >> 2);
        int r1 = r0 + 8;
        #pragma unroll
        for (int nt = 0; nt < 4; nt++) {
            int col = p0 + wn * 32 + nt * 8 + 2 * (lane & 3);
            *(float2*)&ob[(long)r0 * HW + col] =
                make_float2(acc[mt][nt][0], acc[mt][nt][1]);
            *(float2*)&ob[(long)r1 * HW + col] =
                make_float2(acc[mt][nt][2], acc[mt][nt][3]);
        }
    }
}

// ---------------------------------------------------------------------------
// Reduce 9 tap partials + BN + SiLU -> g_z. Vectorized float4.
// ---------------------------------------------------------------------------
__global__ void tap_reduce_kernel(const float* __restrict__ part,
                                  const float* __restrict__ bn,
                                  float* __restrict__ out)
{
    const long PS = (long)BATCH * 256 * HW;
    long idx = (long)blockIdx.x * 256 + threadIdx.x;
    if (idx >= PS / 4) return;
    long e = idx * 4;
    int ch = (int)((e / HW) & 255);

    float v0 = 0.f, v1 = 0.f, v2 = 0.f, v3 = 0.f;
    #pragma unroll
    for (int t = 0; t < 9; t++) {
        float4 a = *(const float4*)&part[(long)t * PS + e];
        v0 += a.x; v1 += a.y; v2 += a.z; v3 += a.w;
    }

    float g = bn[ch], bb = bn[256 + ch], mu = bn[512 + ch], vv = bn[768 + ch];
    float s = g * rsqrtf(vv + 1e-3f);
    float c = bb - mu * s;

    float v[4] = {v0, v1, v2, v3};
    #pragma unroll
    for (int i = 0; i < 4; i++) {
        float t = v[i] * s + c;
        v[i] = t / (1.f + __expf(-t));
    }
    *(float4*)&out[e] = make_float4(v[0], v[1], v[2], v[3]);
}

// ---------------------------------------------------------------------------
// Pack qkv: fp32 -> tf32 bits; add rw+rh positional bias to K channels.
// ---------------------------------------------------------------------------
__global__ void qkv_pack_kernel(const float* __restrict__ in,
                                const float* __restrict__ rw,
                                const float* __restrict__ rh,
                                float* __restrict__ outp)
{
    const long N4 = (long)BATCH * 768 * HW / 4;
    long idx = (long)blockIdx.x * 256 + threadIdx.x;
    if (idx >= N4) return;
    long e = idx * 4;
    int ch = (int)((e / HW) % 768);
    int p  = (int)(e & (HW - 1));

    float4 v = *(const float4*)&in[e];
    float f[4] = {v.x, v.y, v.z, v.w};

    if (ch >= 256 && ch < 512) {
        int hd  = ch - 256;
        int col = p & 31, row = p >> 5;
        const float* rwp = rw + hd * 32;
        float rhv = rh[hd * 32 + row];
        #pragma unroll
        for (int i = 0; i < 4; i++)
            f[i] += rwp[col + i] + rhv;
    }

    uint4 o;
    o.x = f2tf(f[0]); o.y = f2tf(f[1]); o.z = f2tf(f[2]); o.w = f2tf(f[3]);
    *(uint4*)&outp[e] = o;
}

// ---------------------------------------------------------------------------
// tf32 flash attention (unchanged from R10): qkvp holds tf32 bits, bias in K.
// ---------------------------------------------------------------------------
#define QST 72
#define VST 68
#define FA_Q   0
#define FA_KR  (64 * QST)
#define FA_V   (FA_KR + 64 * QST)
#define FA_P   (FA_V + 64 * VST)
#define FA_RED (FA_P + 64 * VST)
#define FA_TOT (FA_RED + 256)

extern __shared__ uint32_t fa_u[];

__global__ __launch_bounds__(256) void flash_tf32_kernel(
    const uint32_t* __restrict__ qkv, float* __restrict__ out)
{
    uint32_t* Qs  = fa_u + FA_Q;
    uint32_t* KRs = fa_u + FA_KR;
    uint32_t* Vs  = fa_u + FA_V;
    uint32_t* Ps  = fa_u + FA_P;
    float* red_max = (float*)(fa_u + FA_RED);
    float* red_sum = red_max + 128;

    const int b  = blockIdx.z;
    const int h  = blockIdx.y;
    const int i0 = blockIdx.x * 64;
    const int tid  = threadIdx.x;
    const int lane = tid & 31, wid = tid >> 5;
    const int wm = wid >> 1;
    const int wn = wid & 1;
    const int lq = lane >> 2;
    const int lr = lane & 3;

    const uint32_t* qb = qkv + ((long)b * 768 + h * 64) * HW;
    const uint32_t* kb = qb + 256 * HW;
    const uint32_t* vb = qb + 512 * HW;

    #pragma unroll
    for (int it = 0; it < 4; it++) {
        int idx = tid + it * 256;
        int d = idx >> 4, i4 = (idx & 15) * 4;
        *(uint4*)&Qs[d * QST + i4] = *(const uint4*)&qb[(long)d * HW + i0 + i4];
    }

    const int row_lo = wm * 16 + lq;
    const int row_hi = row_lo + 8;

    float m_lo = -1e30f, m_hi = -1e30f, l_lo = 0.f, l_hi = 0.f;
    float accO[4][4];
    #pragma unroll
    for (int nt = 0; nt < 4; nt++)
        #pragma unroll
        for (int e = 0; e < 4; e++) accO[nt][e] = 0.f;

    __syncthreads();

    for (int j0 = 0; j0 < HW; j0 += 64) {
        #pragma unroll
        for (int it = 0; it < 4; it++) {
            int idx = tid + it * 256;
            int d = idx >> 4, j4 = (idx & 15) * 4;
            *(uint4*)&KRs[d * QST + j4] = *(const uint4*)&kb[(long)d * HW + j0 + j4];
            *(uint4*)&Vs[d * VST + j4]  = *(const uint4*)&vb[(long)d * HW + j0 + j4];
        }
        __syncthreads();

        float s[4][4];
        #pragma unroll
        for (int nt = 0; nt < 4; nt++)
            #pragma unroll
            for (int e = 0; e < 4; e++) s[nt][e] = 0.f;

        #pragma unroll
        for (int ks = 0; ks < 8; ks++) {
            int d0 = ks * 8 + lr;
            uint32_t a0 = Qs[d0 * QST + row_lo];
            uint32_t a1 = Qs[d0 * QST + row_hi];
            uint32_t a2 = Qs[(d0 + 4) * QST + row_lo];
            uint32_t a3 = Qs[(d0 + 4) * QST + row_hi];
            #pragma unroll
            for (int nt = 0; nt < 4; nt++) {
                int jc = wn * 32 + nt * 8 + lq;
                uint32_t b0 = KRs[d0 * QST + jc];
                uint32_t b1 = KRs[(d0 + 4) * QST + jc];
                mma8(s[nt], a0, a1, a2, a3, b0, b1);
            }
        }

        #pragma unroll
        for (int nt = 0; nt < 4; nt++)
            #pragma unroll
            for (int e = 0; e < 4; e++) s[nt][e] *= 0.125f;

        float mx_lo = -1e30f, mx_hi = -1e30f;
        #pragma unroll
        for (int nt = 0; nt < 4; nt++) {
            mx_lo = fmaxf(mx_lo, fmaxf(s[nt][0], s[nt][1]));
            mx_hi = fmaxf(mx_hi, fmaxf(s[nt][2], s[nt][3]));
        }
        mx_lo = fmaxf(mx_lo, __shfl_xor_sync(0xffffffffu, mx_lo, 1));
        mx_lo = fmaxf(mx_lo, __shfl_xor_sync(0xffffffffu, mx_lo, 2));
        mx_hi = fmaxf(mx_hi, __shfl_xor_sync(0xffffffffu, mx_hi, 1));
        mx_hi = fmaxf(mx_hi, __shfl_xor_sync(0xffffffffu, mx_hi, 2));
        if (lr == 0) {
            red_max[wn * 64 + row_lo] = mx_lo;
            red_max[wn * 64 + row_hi] = mx_hi;
        }
        __syncthreads();
        mx_lo = fmaxf(mx_lo, red_max[(1 - wn) * 64 + row_lo]);
        mx_hi = fmaxf(mx_hi, red_max[(1 - wn) * 64 + row_hi]);

        float mn_lo = fmaxf(m_lo, mx_lo);
        float mn_hi = fmaxf(m_hi, mx_hi);
        float cr_lo = __expf(m_lo - mn_lo);
        float cr_hi = __expf(m_hi - mn_hi);
        m_lo = mn_lo; m_hi = mn_hi;

        float rs_lo = 0.f, rs_hi = 0.f;
        #pragma unroll
        for (int nt = 0; nt < 4; nt++) {
            float p0 = __expf(s[nt][0] - mn_lo);
            float p1 = __expf(s[nt][1] - mn_lo);
            float p2 = __expf(s[nt][2] - mn_hi);
            float p3 = __expf(s[nt][3] - mn_hi);
            rs_lo += p0 + p1;
            rs_hi += p2 + p3;
            int colb = wn * 32 + nt * 8 + 2 * lr;
            *(uint2*)&Ps[row_lo * VST + colb] = make_uint2(f2tf(p0), f2tf(p1));
            *(uint2*)&Ps[row_hi * VST + colb] = make_uint2(f2tf(p2), f2tf(p3));
        }
        rs_lo += __shfl_xor_sync(0xffffffffu, rs_lo, 1);
        rs_lo += __shfl_xor_sync(0xffffffffu, rs_lo, 2);
        rs_hi += __shfl_xor_sync(0xffffffffu, rs_hi, 1);
        rs_hi += __shfl_xor_sync(0xffffffffu, rs_hi, 2);
        if (lr == 0) {
            red_sum[wn * 64 + row_lo] = rs_lo;
            red_sum[wn * 64 + row_hi] = rs_hi;
        }
        __syncthreads();
        rs_lo += red_sum[(1 - wn) * 64 + row_lo];
        rs_hi += red_sum[(1 - wn) * 64 + row_hi];
        l_lo = l_lo * cr_lo + rs_lo;
        l_hi = l_hi * cr_hi + rs_hi;

        #pragma unroll
        for (int nt = 0; nt < 4; nt++) {
            accO[nt][0] *= cr_lo; accO[nt][1] *= cr_lo;
            accO[nt][2] *= cr_hi; accO[nt][3] *= cr_hi;
        }

        #pragma unroll
        for (int ks = 0; ks < 8; ks++) {
            int jj = ks * 8 + lr;
            uint32_t a0 = Ps[row_lo * VST + jj];
            uint32_t a1 = Ps[row_hi * VST + jj];
            uint32_t a2 = Ps[row_lo * VST + jj + 4];
            uint32_t a3 = Ps[row_hi * VST + jj + 4];
            #pragma unroll
            for (int nt = 0; nt < 4; nt++) {
                int dc = wn * 32 + nt * 8 + lq;
                uint32_t b0 = Vs[dc * VST + jj];
                uint32_t b1 = Vs[dc * VST + jj + 4];
                mma8(accO[nt], a0, a1, a2, a3, b0, b1);
            }
        }
        __syncthreads();
    }

    float inv_lo = 1.f / l_lo;
    float inv_hi = 1.f / l_hi;
    float* ob = out + ((long)b * 256 + h * 64) * HW + i0;
    #pragma unroll
    for (int nt = 0; nt < 4; nt++) {
        int d = wn * 32 + nt * 8 + 2 * lr;
        ob[(long)d * HW + row_lo]       = accO[nt][0] * inv_lo;
        ob[(long)(d + 1) * HW + row_lo] = accO[nt][1] * inv_lo;
        ob[(long)d * HW + row_hi]       = accO[nt][2] * inv_hi;
        ob[(long)(d + 1) * HW + row_hi] = accO[nt][3] * inv_hi;
    }
}

// ---------------------------------------------------------------------------
extern "C" void kernel_launch(void* const* d_in, const int* in_sizes, int n_in,
                              void* d_out, int out_size)
{
    const float* x        = (const float*)d_in[0];
    const float* cv1_w    = (const float*)d_in[1];
    const float* cv1_bn   = (const float*)d_in[2];
    const float* cv2_w    = (const float*)d_in[3];
    const float* cv2_bn   = (const float*)d_in[4];
    const float* m_cv1_w  = (const float*)d_in[5];
    const float* m_cv1_bn = (const float*)d_in[6];
    const float* m_qkv_w  = (const float*)d_in[7];
    const float* m_rw     = (const float*)d_in[8];
    const float* m_rh     = (const float*)d_in[9];
    const float* m_cv2_w  = (const float*)d_in[10];
    const float* m_cv2_bn = (const float*)d_in[11];
    float* out = (float*)d_out;

    float *cat, *z, *qkv, *qkvp, *att, *w3, *part;
    cudaGetSymbolAddress((void**)&cat,  g_cat);
    cudaGetSymbolAddress((void**)&z,    g_z);
    cudaGetSymbolAddress((void**)&qkv,  g_qkv);
    cudaGetSymbolAddress((void**)&qkvp, g_qkvp);
    cudaGetSymbolAddress((void**)&att,  g_att);
    cudaGetSymbolAddress((void**)&w3,   g_w3);
    cudaGetSymbolAddress((void**)&part, g_part);

    const int FA_SMEM = FA_TOT * 4;
    cudaFuncSetAttribute(flash_tf32_kernel,
                         cudaFuncAttributeMaxDynamicSharedMemorySize, FA_SMEM);

    const long CAT_S = 1024L * HW;
    const long RED_N  = (long)BATCH * 256 * HW / 4;
    const long PACK_N = (long)BATCH * 768 * HW / 4;

    reorder_w3_kernel<<<(2 * 9 * 65536 + 255) / 256, 256>>>(m_cv1_w, w3);

    // cv1: x (512) -> cat[0:512)
    gemm_tf32_kernel<<<dim3(8, 4, BATCH), 256>>>(
        x, cv1_w, cv1_bn, nullptr, cat,
        512, 512, 512L * HW, CAT_S, 0, 3);

    for (int i = 0; i < 2; i++) {
        const float* yin = cat + (long)(256 + i * 256) * HW;

        // 3x3 conv: 9-way tap split (1152 blocks), then reduce+BN+SiLU
        conv3_part_kernel<<<dim3(8, 18, BATCH), 256>>>(
            yin, w3 + (long)i * 9 * 65536, part, CAT_S);
        tap_reduce_kernel<<<(int)((RED_N + 255) / 256), 256>>>(
            part, m_cv1_bn + i * 4 * 256, z);

        // qkv 1x1 (plain fp32 output)
        gemm_tf32_kernel<<<dim3(8, 6, BATCH), 256>>>(
            z, m_qkv_w + (long)i * 768 * 256, nullptr, nullptr, qkv,
            256, 768, 256L * HW, 768L * HW, 0, 0);

        // pack to tf32 bits, fold rw+rh bias into K
        qkv_pack_kernel<<<(int)((PACK_N + 255) / 256), 256>>>(
            qkv, m_rw + i * 8192, m_rh + i * 8192, qkvp);

        flash_tf32_kernel<<<dim3(16, 4, BATCH), 256, FA_SMEM>>>(
            (const uint32_t*)qkvp, att);

        gemm_tf32_kernel<<<dim3(8, 2, BATCH), 256>>>(
            att, m_cv2_w + (long)i * 256 * 256, m_cv2_bn + i * 4 * 256,
            yin, cat + (long)(512 + i * 256) * HW,
            256, 256, 256L * HW, CAT_S, CAT_S, 7);
    }

    // cv2: cat (1024) -> out (512)
    gemm_tf32_kernel<<<dim3(8, 4, BATCH), 256>>>(
        cat, cv2_w, cv2_bn, nullptr, out,
        1024, 512, CAT_S, 512L * HW, 0, 3);
}

// round 13
// speedup vs baseline: 1.1016x; 1.1016x over previous
#include <cuda_runtime.h>
#include <cstdint>

#define HW 1024
#define BATCH 8

__device__ float g_cat [BATCH * 1024 * HW];
__device__ float g_z   [BATCH * 256  * HW];
__device__ float g_qkv [BATCH * 768  * HW];    // raw fp32 qkv conv output
__device__ float g_qkvp[BATCH * 768  * HW];    // packed tf32 bits (K has bias)
__device__ float g_att [BATCH * 256  * HW];
__device__ float g_w3  [2 * 9 * 256 * 256];    // [i][t][co][ci]
__device__ float g_part[4 * BATCH * 256 * HW]; // conv3 K-segment partials

// ---------------------------------------------------------------------------
__device__ __forceinline__ uint32_t f2tf(float x) {
    uint32_t r;
    asm("cvt.rna.tf32.f32 %0, %1;" : "=r"(r) : "f"(x));
    return r;
}

__device__ __forceinline__ void mma8(float c[4],
    uint32_t a0, uint32_t a1, uint32_t a2, uint32_t a3,
    uint32_t b0, uint32_t b1)
{
    asm volatile(
        "mma.sync.aligned.m16n8k8.row.col.f32.tf32.tf32.f32 "
        "{%0,%1,%2,%3}, {%4,%5,%6,%7}, {%8,%9}, {%0,%1,%2,%3};"
        : "+f"(c[0]), "+f"(c[1]), "+f"(c[2]), "+f"(c[3])
        : "r"(a0), "r"(a1), "r"(a2), "r"(a3), "r"(b0), "r"(b1));
}

#define AST 36
#define BST 136

// ---------------------------------------------------------------------------
__global__ void reorder_w3_kernel(const float* __restrict__ w, float* __restrict__ o)
{
    int idx = blockIdx.x * 256 + threadIdx.x;
    if (idx >= 2 * 9 * 65536) return;
    int i  = idx / (9 * 65536);
    int r  = idx % (9 * 65536);
    int t  = r / 65536;
    int rc = r % 65536;
    int co = rc >> 8, ci = rc & 255;
    o[idx] = w[((long)(i * 256 + co) * 256 + ci) * 9 + t];
}

// ---------------------------------------------------------------------------
__device__ __forceinline__ void mma_chunk(
    const uint32_t* __restrict__ As, const uint32_t* __restrict__ Bs,
    int wm, int wn, int lane, float acc[4][4][4])
{
    #pragma unroll
    for (int ks = 0; ks < 4; ks++) {
        uint32_t a[4][4], bb[4][2];
        int ar = wm * 64 + (lane >> 2);
        int ac = ks * 8 + (lane & 3);
        #pragma unroll
        for (int mt = 0; mt < 4; mt++) {
            int r = ar + mt * 16;
            a[mt][0] = As[r * AST + ac];
            a[mt][1] = As[(r + 8) * AST + ac];
            a[mt][2] = As[r * AST + ac + 4];
            a[mt][3] = As[(r + 8) * AST + ac + 4];
        }
        int br = ks * 8 + (lane & 3);
        int bc = wn * 32 + (lane >> 2);
        #pragma unroll
        for (int nt = 0; nt < 4; nt++) {
            bb[nt][0] = Bs[br * BST + bc + nt * 8];
            bb[nt][1] = Bs[(br + 4) * BST + bc + nt * 8];
        }
        #pragma unroll
        for (int mt = 0; mt < 4; mt++)
            #pragma unroll
            for (int nt = 0; nt < 4; nt++)
                mma8(acc[mt][nt], a[mt][0], a[mt][1], a[mt][2], a[mt][3],
                     bb[nt][0], bb[nt][1]);
    }
}

// ---------------------------------------------------------------------------
// tf32 GEMM for 1x1 convs (exact R8/R10 version).
// flags: 1=BN, 2=SiLU, 4=residual.
// ---------------------------------------------------------------------------
__global__ __launch_bounds__(256) void gemm_tf32_kernel(
    const float* __restrict__ X, const float* __restrict__ W,
    const float* __restrict__ bn, const float* __restrict__ res,
    float* __restrict__ out,
    int Cin, int Cout, long xbS, long obS, long rbS, int flags)
{
    __shared__ uint32_t As[128 * AST];
    __shared__ uint32_t Bs[32 * BST];

    const int b   = blockIdx.z;
    const int p0  = blockIdx.x * 128;
    const int co0 = blockIdx.y * 128;
    const int tid = threadIdx.x;
    const int lane = tid & 31, wid = tid >> 5;
    const int wm = wid >> 2, wn = wid & 3;

    const float* Xb = X + (long)b * xbS;

    float acc[4][4][4];
    #pragma unroll
    for (int mt = 0; mt < 4; mt++)
        #pragma unroll
        for (int nt = 0; nt < 4; nt++)
            #pragma unroll
            for (int e = 0; e < 4; e++) acc[mt][nt][e] = 0.f;

    for (int k0 = 0; k0 < Cin; k0 += 32) {
        #pragma unroll
        for (int it = 0; it < 4; it++) {
            int r = (tid >> 3) + it * 32;
            int c = (tid & 7) * 4;
            float4 v = *(const float4*)&W[(long)(co0 + r) * Cin + k0 + c];
            As[r * AST + c + 0] = f2tf(v.x);
            As[r * AST + c + 1] = f2tf(v.y);
            As[r * AST + c + 2] = f2tf(v.z);
            As[r * AST + c + 3] = f2tf(v.w);
        }
        #pragma unroll
        for (int it = 0; it < 4; it++) {
            int kk = (tid >> 5) + it * 8;
            int pp = lane * 4;
            float4 v = *(const float4*)&Xb[(long)(k0 + kk) * HW + p0 + pp];
            Bs[kk * BST + pp + 0] = f2tf(v.x);
            Bs[kk * BST + pp + 1] = f2tf(v.y);
            Bs[kk * BST + pp + 2] = f2tf(v.z);
            Bs[kk * BST + pp + 3] = f2tf(v.w);
        }
        __syncthreads();
        mma_chunk(As, Bs, wm, wn, lane, acc);
        __syncthreads();
    }

    #pragma unroll
    for (int mt = 0; mt < 4; mt++) {
        int r0 = co0 + wm * 64 + mt * 16 + (lane >> 2);
        int r1 = r0 + 8;
        float s0 = 1.f, c0 = 0.f, s1 = 1.f, c1 = 0.f;
        if (flags & 1) {
            float g0 = bn[r0], b0v = bn[Cout + r0], m0 = bn[2*Cout + r0], v0 = bn[3*Cout + r0];
            s0 = g0 * rsqrtf(v0 + 1e-3f); c0 = b0v - m0 * s0;
            float g1 = bn[r1], b1v = bn[Cout + r1], m1 = bn[2*Cout + r1], v1 = bn[3*Cout + r1];
            s1 = g1 * rsqrtf(v1 + 1e-3f); c1 = b1v - m1 * s1;
        }
        #pragma unroll
        for (int nt = 0; nt < 4; nt++) {
            int col = p0 + wn * 32 + nt * 8 + 2 * (lane & 3);
            float v00 = acc[mt][nt][0] * s0 + c0;
            float v01 = acc[mt][nt][1] * s0 + c0;
            float v10 = acc[mt][nt][2] * s1 + c1;
            float v11 = acc[mt][nt][3] * s1 + c1;
            if (flags & 2) {
                v00 = v00 / (1.f + __expf(-v00));
                v01 = v01 / (1.f + __expf(-v01));
                v10 = v10 / (1.f + __expf(-v10));
                v11 = v11 / (1.f + __expf(-v11));
            }
            if (flags & 4) {
                const float* rb = res + (long)b * rbS;
                v00 += rb[(long)r0 * HW + col];
                v01 += rb[(long)r0 * HW + col + 1];
                v10 += rb[(long)r1 * HW + col];
                v11 += rb[(long)r1 * HW + col + 1];
            }
            float* ob = out + (long)b * obS;
            *(float2*)&ob[(long)r0 * HW + col] = make_float2(v00, v01);
            *(float2*)&ob[(long)r1 * HW + col] = make_float2(v10, v11);
        }
    }
}

// ---------------------------------------------------------------------------
// K-split tf32 3x3 conv: 72 chunks (9 taps x 8 k-chunks) split into 4
// contiguous segments of 18. grid (8, 2*4, BATCH) = 512 blocks.
// Partials layout: g_part[seg][b][co][p]. Traffic: 4 x 8 MB.
// ---------------------------------------------------------------------------
__global__ __launch_bounds__(256) void conv3_part_kernel(
    const float* __restrict__ X, const float* __restrict__ Wt,
    float* __restrict__ part_out, long xbS)
{
    __shared__ uint32_t As[128 * AST];
    __shared__ uint32_t Bs[32 * BST];

    const int b    = blockIdx.z;
    const int p0   = blockIdx.x * 128;
    const int seg  = blockIdx.y >> 1;
    const int co0  = (blockIdx.y & 1) * 128;
    const int tid  = threadIdx.x;
    const int lane = tid & 31, wid = tid >> 5;
    const int wm = wid >> 2, wn = wid & 3;

    const float* Xb = X + (long)b * xbS;

    float acc[4][4][4];
    #pragma unroll
    for (int mt = 0; mt < 4; mt++)
        #pragma unroll
        for (int nt = 0; nt < 4; nt++)
            #pragma unroll
            for (int e = 0; e < 4; e++) acc[mt][nt][e] = 0.f;

    const int c0 = seg * 18;
    for (int c = c0; c < c0 + 18; c++) {
        const int t  = c >> 3;            // tap 0..8
        const int kc = (c & 7) * 32;      // k-chunk within tap
        const int dy = t / 3 - 1, dx = t % 3 - 1;
        const float* Wtt = Wt + t * 65536;

        #pragma unroll
        for (int it = 0; it < 4; it++) {
            int r = (tid >> 3) + it * 32;
            int cc = (tid & 7) * 4;
            float4 v = *(const float4*)&Wtt[(long)(co0 + r) * 256 + kc + cc];
            As[r * AST + cc + 0] = f2tf(v.x);
            As[r * AST + cc + 1] = f2tf(v.y);
            As[r * AST + cc + 2] = f2tf(v.z);
            As[r * AST + cc + 3] = f2tf(v.w);
        }
        #pragma unroll
        for (int e = tid; e < 4096; e += 256) {
            int kk = e >> 7, p = e & 127;
            int pix = p0 + p;
            int row = (pix >> 5) + dy;
            int col = (pix & 31) + dx;
            float xv = 0.f;
            if ((unsigned)row < 32u && (unsigned)col < 32u)
                xv = Xb[(long)(kc + kk) * HW + row * 32 + col];
            Bs[kk * BST + p] = f2tf(xv);
        }
        __syncthreads();
        mma_chunk(As, Bs, wm, wn, lane, acc);
        __syncthreads();
    }

    float* ob = part_out + ((long)seg * BATCH + b) * 256 * HW;
    #pragma unroll
    for (int mt = 0; mt < 4; mt++) {
        int r0 = co0 + wm * 64 + mt * 16 + (lane >> 2);
        int r1 = r0 + 8;
        #pragma unroll
        for (int nt = 0; nt < 4; nt++) {
            int col = p0 + wn * 32 + nt * 8 + 2 * (lane & 3);
            *(float2*)&ob[(long)r0 * HW + col] =
                make_float2(acc[mt][nt][0], acc[mt][nt][1]);
            *(float2*)&ob[(long)r1 * HW + col] =
                make_float2(acc[mt][nt][2], acc[mt][nt][3]);
        }
    }
}

// ---------------------------------------------------------------------------
// Reduce 4 segment partials + BN + SiLU -> g_z. Vectorized float4.
// ---------------------------------------------------------------------------
__global__ void tap_reduce_kernel(const float* __restrict__ part,
                                  const float* __restrict__ bn,
                                  float* __restrict__ out)
{
    const long PS = (long)BATCH * 256 * HW;
    long idx = (long)blockIdx.x * 256 + threadIdx.x;
    if (idx >= PS / 4) return;
    long e = idx * 4;
    int ch = (int)((e / HW) & 255);

    float v0 = 0.f, v1 = 0.f, v2 = 0.f, v3 = 0.f;
    #pragma unroll
    for (int t = 0; t < 4; t++) {
        float4 a = *(const float4*)&part[(long)t * PS + e];
        v0 += a.x; v1 += a.y; v2 += a.z; v3 += a.w;
    }

    float g = bn[ch], bb = bn[256 + ch], mu = bn[512 + ch], vv = bn[768 + ch];
    float s = g * rsqrtf(vv + 1e-3f);
    float c = bb - mu * s;

    float v[4] = {v0, v1, v2, v3};
    #pragma unroll
    for (int i = 0; i < 4; i++) {
        float t = v[i] * s + c;
        v[i] = t / (1.f + __expf(-t));
    }
    *(float4*)&out[e] = make_float4(v[0], v[1], v[2], v[3]);
}

// ---------------------------------------------------------------------------
// Pack qkv: fp32 -> tf32 bits; add rw+rh positional bias to K channels.
// ---------------------------------------------------------------------------
__global__ void qkv_pack_kernel(const float* __restrict__ in,
                                const float* __restrict__ rw,
                                const float* __restrict__ rh,
                                float* __restrict__ outp)
{
    const long N4 = (long)BATCH * 768 * HW / 4;
    long idx = (long)blockIdx.x * 256 + threadIdx.x;
    if (idx >= N4) return;
    long e = idx * 4;
    int ch = (int)((e / HW) % 768);
    int p  = (int)(e & (HW - 1));

    float4 v = *(const float4*)&in[e];
    float f[4] = {v.x, v.y, v.z, v.w};

    if (ch >= 256 && ch < 512) {
        int hd  = ch - 256;
        int col = p & 31, row = p >> 5;
        const float* rwp = rw + hd * 32;
        float rhv = rh[hd * 32 + row];
        #pragma unroll
        for (int i = 0; i < 4; i++)
            f[i] += rwp[col + i] + rhv;
    }

    uint4 o;
    o.x = f2tf(f[0]); o.y = f2tf(f[1]); o.z = f2tf(f[2]); o.w = f2tf(f[3]);
    *(uint4*)&outp[e] = o;
}

// ---------------------------------------------------------------------------
// tf32 flash attention (unchanged from R10): qkvp holds tf32 bits, bias in K.
// ---------------------------------------------------------------------------
#define QST 72
#define VST 68
#define FA_Q   0
#define FA_KR  (64 * QST)
#define FA_V   (FA_KR + 64 * QST)
#define FA_P   (FA_V + 64 * VST)
#define FA_RED (FA_P + 64 * VST)
#define FA_TOT (FA_RED + 256)

extern __shared__ uint32_t fa_u[];

__global__ __launch_bounds__(256) void flash_tf32_kernel(
    const uint32_t* __restrict__ qkv, float* __restrict__ out)
{
    uint32_t* Qs  = fa_u + FA_Q;
    uint32_t* KRs = fa_u + FA_KR;
    uint32_t* Vs  = fa_u + FA_V;
    uint32_t* Ps  = fa_u + FA_P;
    float* red_max = (float*)(fa_u + FA_RED);
    float* red_sum = red_max + 128;

    const int b  = blockIdx.z;
    const int h  = blockIdx.y;
    const int i0 = blockIdx.x * 64;
    const int tid  = threadIdx.x;
    const int lane = tid & 31, wid = tid >> 5;
    const int wm = wid >> 1;
    const int wn = wid & 1;
    const int lq = lane >> 2;
    const int lr = lane & 3;

    const uint32_t* qb = qkv + ((long)b * 768 + h * 64) * HW;
    const uint32_t* kb = qb + 256 * HW;
    const uint32_t* vb = qb + 512 * HW;

    #pragma unroll
    for (int it = 0; it < 4; it++) {
        int idx = tid + it * 256;
        int d = idx >> 4, i4 = (idx & 15) * 4;
        *(uint4*)&Qs[d * QST + i4] = *(const uint4*)&qb[(long)d * HW + i0 + i4];
    }

    const int row_lo = wm * 16 + lq;
    const int row_hi = row_lo + 8;

    float m_lo = -1e30f, m_hi = -1e30f, l_lo = 0.f, l_hi = 0.f;
    float accO[4][4];
    #pragma unroll
    for (int nt = 0; nt < 4; nt++)
        #pragma unroll
        for (int e = 0; e < 4; e++) accO[nt][e] = 0.f;

    __syncthreads();

    for (int j0 = 0; j0 < HW; j0 += 64) {
        #pragma unroll
        for (int it = 0; it < 4; it++) {
            int idx = tid + it * 256;
            int d = idx >> 4, j4 = (idx & 15) * 4;
            *(uint4*)&KRs[d * QST + j4] = *(const uint4*)&kb[(long)d * HW + j0 + j4];
            *(uint4*)&Vs[d * VST + j4]  = *(const uint4*)&vb[(long)d * HW + j0 + j4];
        }
        __syncthreads();

        float s[4][4];
        #pragma unroll
        for (int nt = 0; nt < 4; nt++)
            #pragma unroll
            for (int e = 0; e < 4; e++) s[nt][e] = 0.f;

        #pragma unroll
        for (int ks = 0; ks < 8; ks++) {
            int d0 = ks * 8 + lr;
            uint32_t a0 = Qs[d0 * QST + row_lo];
            uint32_t a1 = Qs[d0 * QST + row_hi];
            uint32_t a2 = Qs[(d0 + 4) * QST + row_lo];
            uint32_t a3 = Qs[(d0 + 4) * QST + row_hi];
            #pragma unroll
            for (int nt = 0; nt < 4; nt++) {
                int jc = wn * 32 + nt * 8 + lq;
                uint32_t b0 = KRs[d0 * QST + jc];
                uint32_t b1 = KRs[(d0 + 4) * QST + jc];
                mma8(s[nt], a0, a1, a2, a3, b0, b1);
            }
        }

        #pragma unroll
        for (int nt = 0; nt < 4; nt++)
            #pragma unroll
            for (int e = 0; e < 4; e++) s[nt][e] *= 0.125f;

        float mx_lo = -1e30f, mx_hi = -1e30f;
        #pragma unroll
        for (int nt = 0; nt < 4; nt++) {
            mx_lo = fmaxf(mx_lo, fmaxf(s[nt][0], s[nt][1]));
            mx_hi = fmaxf(mx_hi, fmaxf(s[nt][2], s[nt][3]));
        }
        mx_lo = fmaxf(mx_lo, __shfl_xor_sync(0xffffffffu, mx_lo, 1));
        mx_lo = fmaxf(mx_lo, __shfl_xor_sync(0xffffffffu, mx_lo, 2));
        mx_hi = fmaxf(mx_hi, __shfl_xor_sync(0xffffffffu, mx_hi, 1));
        mx_hi = fmaxf(mx_hi, __shfl_xor_sync(0xffffffffu, mx_hi, 2));
        if (lr == 0) {
            red_max[wn * 64 + row_lo] = mx_lo;
            red_max[wn * 64 + row_hi] = mx_hi;
        }
        __syncthreads();
        mx_lo = fmaxf(mx_lo, red_max[(1 - wn) * 64 + row_lo]);
        mx_hi = fmaxf(mx_hi, red_max[(1 - wn) * 64 + row_hi]);

        float mn_lo = fmaxf(m_lo, mx_lo);
        float mn_hi = fmaxf(m_hi, mx_hi);
        float cr_lo = __expf(m_lo - mn_lo);
        float cr_hi = __expf(m_hi - mn_hi);
        m_lo = mn_lo; m_hi = mn_hi;

        float rs_lo = 0.f, rs_hi = 0.f;
        #pragma unroll
        for (int nt = 0; nt < 4; nt++) {
            float p0 = __expf(s[nt][0] - mn_lo);
            float p1 = __expf(s[nt][1] - mn_lo);
            float p2 = __expf(s[nt][2] - mn_hi);
            float p3 = __expf(s[nt][3] - mn_hi);
            rs_lo += p0 + p1;
            rs_hi += p2 + p3;
            int colb = wn * 32 + nt * 8 + 2 * lr;
            *(uint2*)&Ps[row_lo * VST + colb] = make_uint2(f2tf(p0), f2tf(p1));
            *(uint2*)&Ps[row_hi * VST + colb] = make_uint2(f2tf(p2), f2tf(p3));
        }
        rs_lo += __shfl_xor_sync(0xffffffffu, rs_lo, 1);
        rs_lo += __shfl_xor_sync(0xffffffffu, rs_lo, 2);
        rs_hi += __shfl_xor_sync(0xffffffffu, rs_hi, 1);
        rs_hi += __shfl_xor_sync(0xffffffffu, rs_hi, 2);
        if (lr == 0) {
            red_sum[wn * 64 + row_lo] = rs_lo;
            red_sum[wn * 64 + row_hi] = rs_hi;
        }
        __syncthreads();
        rs_lo += red_sum[(1 - wn) * 64 + row_lo];
        rs_hi += red_sum[(1 - wn) * 64 + row_hi];
        l_lo = l_lo * cr_lo + rs_lo;
        l_hi = l_hi * cr_hi + rs_hi;

        #pragma unroll
        for (int nt = 0; nt < 4; nt++) {
            accO[nt][0] *= cr_lo; accO[nt][1] *= cr_lo;
            accO[nt][2] *= cr_hi; accO[nt][3] *= cr_hi;
        }

        #pragma unroll
        for (int ks = 0; ks < 8; ks++) {
            int jj = ks * 8 + lr;
            uint32_t a0 = Ps[row_lo * VST + jj];
            uint32_t a1 = Ps[row_hi * VST + jj];
            uint32_t a2 = Ps[row_lo * VST + jj + 4];
            uint32_t a3 = Ps[row_hi * VST + jj + 4];
            #pragma unroll
            for (int nt = 0; nt < 4; nt++) {
                int dc = wn * 32 + nt * 8 + lq;
                uint32_t b0 = Vs[dc * VST + jj];
                uint32_t b1 = Vs[dc * VST + jj + 4];
                mma8(accO[nt], a0, a1, a2, a3, b0, b1);
            }
        }
        __syncthreads();
    }

    float inv_lo = 1.f / l_lo;
    float inv_hi = 1.f / l_hi;
    float* ob = out + ((long)b * 256 + h * 64) * HW + i0;
    #pragma unroll
    for (int nt = 0; nt < 4; nt++) {
        int d = wn * 32 + nt * 8 + 2 * lr;
        ob[(long)d * HW + row_lo]       = accO[nt][0] * inv_lo;
        ob[(long)(d + 1) * HW + row_lo] = accO[nt][1] * inv_lo;
        ob[(long)d * HW + row_hi]       = accO[nt][2] * inv_hi;
        ob[(long)(d + 1) * HW + row_hi] = accO[nt][3] * inv_hi;
    }
}

// ---------------------------------------------------------------------------
extern "C" void kernel_launch(void* const* d_in, const int* in_sizes, int n_in,
                              void* d_out, int out_size)
{
    const float* x        = (const float*)d_in[0];
    const float* cv1_w    = (const float*)d_in[1];
    const float* cv1_bn   = (const float*)d_in[2];
    const float* cv2_w    = (const float*)d_in[3];
    const float* cv2_bn   = (const float*)d_in[4];
    const float* m_cv1_w  = (const float*)d_in[5];
    const float* m_cv1_bn = (const float*)d_in[6];
    const float* m_qkv_w  = (const float*)d_in[7];
    const float* m_rw     = (const float*)d_in[8];
    const float* m_rh     = (const float*)d_in[9];
    const float* m_cv2_w  = (const float*)d_in[10];
    const float* m_cv2_bn = (const float*)d_in[11];
    float* out = (float*)d_out;

    float *cat, *z, *qkv, *qkvp, *att, *w3, *part;
    cudaGetSymbolAddress((void**)&cat,  g_cat);
    cudaGetSymbolAddress((void**)&z,    g_z);
    cudaGetSymbolAddress((void**)&qkv,  g_qkv);
    cudaGetSymbolAddress((void**)&qkvp, g_qkvp);
    cudaGetSymbolAddress((void**)&att,  g_att);
    cudaGetSymbolAddress((void**)&w3,   g_w3);
    cudaGetSymbolAddress((void**)&part, g_part);

    const int FA_SMEM = FA_TOT * 4;
    cudaFuncSetAttribute(flash_tf32_kernel,
                         cudaFuncAttributeMaxDynamicSharedMemorySize, FA_SMEM);

    const long CAT_S = 1024L * HW;
    const long RED_N  = (long)BATCH * 256 * HW / 4;
    const long PACK_N = (long)BATCH * 768 * HW / 4;

    reorder_w3_kernel<<<(2 * 9 * 65536 + 255) / 256, 256>>>(m_cv1_w, w3);

    // cv1: x (512) -> cat[0:512)
    gemm_tf32_kernel<<<dim3(8, 4, BATCH), 256>>>(
        x, cv1_w, cv1_bn, nullptr, cat,
        512, 512, 512L * HW, CAT_S, 0, 3);

    for (int i = 0; i < 2; i++) {
        const float* yin = cat + (long)(256 + i * 256) * HW;

        // 3x3 conv: 4-way K-split (512 blocks), then reduce+BN+SiLU
        conv3_part_kernel<<<dim3(8, 8, BATCH), 256>>>(
            yin, w3 + (long)i * 9 * 65536, part, CAT_S);
        tap_reduce_kernel<<<(int)((RED_N + 255) / 256), 256>>>(
            part, m_cv1_bn + i * 4 * 256, z);

        // qkv 1x1 (plain fp32 output)
        gemm_tf32_kernel<<<dim3(8, 6, BATCH), 256>>>(
            z, m_qkv_w + (long)i * 768 * 256, nullptr, nullptr, qkv,
            256, 768, 256L * HW, 768L * HW, 0, 0);

        // pack to tf32 bits, fold rw+rh bias into K
        qkv_pack_kernel<<<(int)((PACK_N + 255) / 256), 256>>>(
            qkv, m_rw + i * 8192, m_rh + i * 8192, qkvp);

        flash_tf32_kernel<<<dim3(16, 4, BATCH), 256, FA_SMEM>>>(
            (const uint32_t*)qkvp, att);

        gemm_tf32_kernel<<<dim3(8, 2, BATCH), 256>>>(
            att, m_cv2_w + (long)i * 256 * 256, m_cv2_bn + i * 4 * 256,
            yin, cat + (long)(512 + i * 256) * HW,
            256, 256, 256L * HW, CAT_S, CAT_S, 7);
    }

    // cv2: cat (1024) -> out (512)
    gemm_tf32_kernel<<<dim3(8, 4, BATCH), 256>>>(
        cat, cv2_w, cv2_bn, nullptr, out,
        1024, 512, CAT_S, 512L * HW, 0, 3);
}

// round 15
// speedup vs baseline: 1.1130x; 1.0103x over previous
#include <cuda_runtime.h>
#include <cstdint>

#define HW 1024
#define BATCH 8

__device__ float g_cat [BATCH * 1024 * HW];
__device__ float g_z   [BATCH * 256  * HW];
__device__ float g_qkv [BATCH * 768  * HW];    // raw fp32 qkv conv output
__device__ float g_qkvp[BATCH * 768  * HW];    // packed tf32 bits (K has bias)
__device__ float g_att [BATCH * 256  * HW];
__device__ float g_w3  [2 * 9 * 256 * 256];    // [i][t][co][ci]
__device__ float g_part[2 * BATCH * 256 * HW]; // conv3 K-segment partials

// ---------------------------------------------------------------------------
__device__ __forceinline__ uint32_t f2tf(float x) {
    uint32_t r;
    asm("cvt.rna.tf32.f32 %0, %1;" : "=r"(r) : "f"(x));
    return r;
}

__device__ __forceinline__ void mma8(float c[4],
    uint32_t a0, uint32_t a1, uint32_t a2, uint32_t a3,
    uint32_t b0, uint32_t b1)
{
    asm volatile(
        "mma.sync.aligned.m16n8k8.row.col.f32.tf32.tf32.f32 "
        "{%0,%1,%2,%3}, {%4,%5,%6,%7}, {%8,%9}, {%0,%1,%2,%3};"
        : "+f"(c[0]), "+f"(c[1]), "+f"(c[2]), "+f"(c[3])
        : "r"(a0), "r"(a1), "r"(a2), "r"(a3), "r"(b0), "r"(b1));
}

#define AST 36
#define BST 136

// ---------------------------------------------------------------------------
__global__ void reorder_w3_kernel(const float* __restrict__ w, float* __restrict__ o)
{
    int idx = blockIdx.x * 256 + threadIdx.x;
    if (idx >= 2 * 9 * 65536) return;
    int i  = idx / (9 * 65536);
    int r  = idx % (9 * 65536);
    int t  = r / 65536;
    int rc = r % 65536;
    int co = rc >> 8, ci = rc & 255;
    o[idx] = w[((long)(i * 256 + co) * 256 + ci) * 9 + t];
}

// ---------------------------------------------------------------------------
__device__ __forceinline__ void mma_chunk(
    const uint32_t* __restrict__ As, const uint32_t* __restrict__ Bs,
    int wm, int wn, int lane, float acc[4][4][4])
{
    #pragma unroll
    for (int ks = 0; ks < 4; ks++) {
        uint32_t a[4][4], bb[4][2];
        int ar = wm * 64 + (lane >> 2);
        int ac = ks * 8 + (lane & 3);
        #pragma unroll
        for (int mt = 0; mt < 4; mt++) {
            int r = ar + mt * 16;
            a[mt][0] = As[r * AST + ac];
            a[mt][1] = As[(r + 8) * AST + ac];
            a[mt][2] = As[r * AST + ac + 4];
            a[mt][3] = As[(r + 8) * AST + ac + 4];
        }
        int br = ks * 8 + (lane & 3);
        int bc = wn * 32 + (lane >> 2);
        #pragma unroll
        for (int nt = 0; nt < 4; nt++) {
            bb[nt][0] = Bs[br * BST + bc + nt * 8];
            bb[nt][1] = Bs[(br + 4) * BST + bc + nt * 8];
        }
        #pragma unroll
        for (int mt = 0; mt < 4; mt++)
            #pragma unroll
            for (int nt = 0; nt < 4; nt++)
                mma8(acc[mt][nt], a[mt][0], a[mt][1], a[mt][2], a[mt][3],
                     bb[nt][0], bb[nt][1]);
    }
}

// ---------------------------------------------------------------------------
// tf32 GEMM for 1x1 convs (exact R8/R10 version).
// flags: 1=BN, 2=SiLU, 4=residual.
// ---------------------------------------------------------------------------
__global__ __launch_bounds__(256) void gemm_tf32_kernel(
    const float* __restrict__ X, const float* __restrict__ W,
    const float* __restrict__ bn, const float* __restrict__ res,
    float* __restrict__ out,
    int Cin, int Cout, long xbS, long obS, long rbS, int flags)
{
    __shared__ uint32_t As[128 * AST];
    __shared__ uint32_t Bs[32 * BST];

    const int b   = blockIdx.z;
    const int p0  = blockIdx.x * 128;
    const int co0 = blockIdx.y * 128;
    const int tid = threadIdx.x;
    const int lane = tid & 31, wid = tid >> 5;
    const int wm = wid >> 2, wn = wid & 3;

    const float* Xb = X + (long)b * xbS;

    float acc[4][4][4];
    #pragma unroll
    for (int mt = 0; mt < 4; mt++)
        #pragma unroll
        for (int nt = 0; nt < 4; nt++)
            #pragma unroll
            for (int e = 0; e < 4; e++) acc[mt][nt][e] = 0.f;

    for (int k0 = 0; k0 < Cin; k0 += 32) {
        #pragma unroll
        for (int it = 0; it < 4; it++) {
            int r = (tid >> 3) + it * 32;
            int c = (tid & 7) * 4;
            float4 v = *(const float4*)&W[(long)(co0 + r) * Cin + k0 + c];
            As[r * AST + c + 0] = f2tf(v.x);
            As[r * AST + c + 1] = f2tf(v.y);
            As[r * AST + c + 2] = f2tf(v.z);
            As[r * AST + c + 3] = f2tf(v.w);
        }
        #pragma unroll
        for (int it = 0; it < 4; it++) {
            int kk = (tid >> 5) + it * 8;
            int pp = lane * 4;
            float4 v = *(const float4*)&Xb[(long)(k0 + kk) * HW + p0 + pp];
            Bs[kk * BST + pp + 0] = f2tf(v.x);
            Bs[kk * BST + pp + 1] = f2tf(v.y);
            Bs[kk * BST + pp + 2] = f2tf(v.z);
            Bs[kk * BST + pp + 3] = f2tf(v.w);
        }
        __syncthreads();
        mma_chunk(As, Bs, wm, wn, lane, acc);
        __syncthreads();
    }

    #pragma unroll
    for (int mt = 0; mt < 4; mt++) {
        int r0 = co0 + wm * 64 + mt * 16 + (lane >> 2);
        int r1 = r0 + 8;
        float s0 = 1.f, c0 = 0.f, s1 = 1.f, c1 = 0.f;
        if (flags & 1) {
            float g0 = bn[r0], b0v = bn[Cout + r0], m0 = bn[2*Cout + r0], v0 = bn[3*Cout + r0];
            s0 = g0 * rsqrtf(v0 + 1e-3f); c0 = b0v - m0 * s0;
            float g1 = bn[r1], b1v = bn[Cout + r1], m1 = bn[2*Cout + r1], v1 = bn[3*Cout + r1];
            s1 = g1 * rsqrtf(v1 + 1e-3f); c1 = b1v - m1 * s1;
        }
        #pragma unroll
        for (int nt = 0; nt < 4; nt++) {
            int col = p0 + wn * 32 + nt * 8 + 2 * (lane & 3);
            float v00 = acc[mt][nt][0] * s0 + c0;
            float v01 = acc[mt][nt][1] * s0 + c0;
            float v10 = acc[mt][nt][2] * s1 + c1;
            float v11 = acc[mt][nt][3] * s1 + c1;
            if (flags & 2) {
                v00 = v00 / (1.f + __expf(-v00));
                v01 = v01 / (1.f + __expf(-v01));
                v10 = v10 / (1.f + __expf(-v10));
                v11 = v11 / (1.f + __expf(-v11));
            }
            if (flags & 4) {
                const float* rb = res + (long)b * rbS;
                v00 += rb[(long)r0 * HW + col];
                v01 += rb[(long)r0 * HW + col + 1];
                v10 += rb[(long)r1 * HW + col];
                v11 += rb[(long)r1 * HW + col + 1];
            }
            float* ob = out + (long)b * obS;
            *(float2*)&ob[(long)r0 * HW + col] = make_float2(v00, v01);
            *(float2*)&ob[(long)r1 * HW + col] = make_float2(v10, v11);
        }
    }
}

// ---------------------------------------------------------------------------
// K-split tf32 3x3 conv: 72 chunks split into 2 segments of 36.
// grid (8, 2*2, BATCH) = 256 blocks -> single wave at 2 CTA/SM.
// Partials: g_part[seg][b][co][p], 2 x 8 MB.
// ---------------------------------------------------------------------------
__global__ __launch_bounds__(256) void conv3_part_kernel(
    const float* __restrict__ X, const float* __restrict__ Wt,
    float* __restrict__ part_out, long xbS)
{
    __shared__ uint32_t As[128 * AST];
    __shared__ uint32_t Bs[32 * BST];

    const int b    = blockIdx.z;
    const int p0   = blockIdx.x * 128;
    const int seg  = blockIdx.y >> 1;
    const int co0  = (blockIdx.y & 1) * 128;
    const int tid  = threadIdx.x;
    const int lane = tid & 31, wid = tid >> 5;
    const int wm = wid >> 2, wn = wid & 3;

    const float* Xb = X + (long)b * xbS;

    float acc[4][4][4];
    #pragma unroll
    for (int mt = 0; mt < 4; mt++)
        #pragma unroll
        for (int nt = 0; nt < 4; nt++)
            #pragma unroll
            for (int e = 0; e < 4; e++) acc[mt][nt][e] = 0.f;

    const int c0 = seg * 36;
    for (int c = c0; c < c0 + 36; c++) {
        const int t  = c >> 3;            // tap 0..8
        const int kc = (c & 7) * 32;      // k-chunk within tap
        const int dy = t / 3 - 1, dx = t % 3 - 1;
        const float* Wtt = Wt + t * 65536;

        #pragma unroll
        for (int it = 0; it < 4; it++) {
            int r = (tid >> 3) + it * 32;
            int cc = (tid & 7) * 4;
            float4 v = *(const float4*)&Wtt[(long)(co0 + r) * 256 + kc + cc];
            As[r * AST + cc + 0] = f2tf(v.x);
            As[r * AST + cc + 1] = f2tf(v.y);
            As[r * AST + cc + 2] = f2tf(v.z);
            As[r * AST + cc + 3] = f2tf(v.w);
        }
        #pragma unroll
        for (int e = tid; e < 4096; e += 256) {
            int kk = e >> 7, p = e & 127;
            int pix = p0 + p;
            int row = (pix >> 5) + dy;
            int col = (pix & 31) + dx;
            float xv = 0.f;
            if ((unsigned)row < 32u && (unsigned)col < 32u)
                xv = Xb[(long)(kc + kk) * HW + row * 32 + col];
            Bs[kk * BST + p] = f2tf(xv);
        }
        __syncthreads();
        mma_chunk(As, Bs, wm, wn, lane, acc);
        __syncthreads();
    }

    float* ob = part_out + ((long)seg * BATCH + b) * 256 * HW;
    #pragma unroll
    for (int mt = 0; mt < 4; mt++) {
        int r0 = co0 + wm * 64 + mt * 16 + (lane >> 2);
        int r1 = r0 + 8;
        #pragma unroll
        for (int nt = 0; nt < 4; nt++) {
            int col = p0 + wn * 32 + nt * 8 + 2 * (lane & 3);
            *(float2*)&ob[(long)r0 * HW + col] =
                make_float2(acc[mt][nt][0], acc[mt][nt][1]);
            *(float2*)&ob[(long)r1 * HW + col] =
                make_float2(acc[mt][nt][2], acc[mt][nt][3]);
        }
    }
}

// ---------------------------------------------------------------------------
// Reduce 2 segment partials + BN + SiLU -> g_z.
// ---------------------------------------------------------------------------
__global__ void tap_reduce_kernel(const float* __restrict__ part,
                                  const float* __restrict__ bn,
                                  float* __restrict__ out)
{
    const long PS = (long)BATCH * 256 * HW;
    long idx = (long)blockIdx.x * 256 + threadIdx.x;
    if (idx >= PS / 4) return;
    long e = idx * 4;
    int ch = (int)((e / HW) & 255);

    float4 a = *(const float4*)&part[e];
    float4 b4 = *(const float4*)&part[PS + e];

    float g = bn[ch], bb = bn[256 + ch], mu = bn[512 + ch], vv = bn[768 + ch];
    float s = g * rsqrtf(vv + 1e-3f);
    float c = bb - mu * s;

    float v[4] = {a.x + b4.x, a.y + b4.y, a.z + b4.z, a.w + b4.w};
    #pragma unroll
    for (int i = 0; i < 4; i++) {
        float t = v[i] * s + c;
        v[i] = t / (1.f + __expf(-t));
    }
    *(float4*)&out[e] = make_float4(v[0], v[1], v[2], v[3]);
}

// ---------------------------------------------------------------------------
// Pack qkv: fp32 -> tf32 bits; add rw+rh positional bias to K channels.
// ---------------------------------------------------------------------------
__global__ void qkv_pack_kernel(const float* __restrict__ in,
                                const float* __restrict__ rw,
                                const float* __restrict__ rh,
                                float* __restrict__ outp)
{
    const long N4 = (long)BATCH * 768 * HW / 4;
    long idx = (long)blockIdx.x * 256 + threadIdx.x;
    if (idx >= N4) return;
    long e = idx * 4;
    int ch = (int)((e / HW) % 768);
    int p  = (int)(e & (HW - 1));

    float4 v = *(const float4*)&in[e];
    float f[4] = {v.x, v.y, v.z, v.w};

    if (ch >= 256 && ch < 512) {
        int hd  = ch - 256;
        int col = p & 31, row = p >> 5;
        const float* rwp = rw + hd * 32;
        float rhv = rh[hd * 32 + row];
        #pragma unroll
        for (int i = 0; i < 4; i++)
            f[i] += rwp[col + i] + rhv;
    }

    uint4 o;
    o.x = f2tf(f[0]); o.y = f2tf(f[1]); o.z = f2tf(f[2]); o.w = f2tf(f[3]);
    *(uint4*)&outp[e] = o;
}

// ---------------------------------------------------------------------------
// tf32 flash attention with double-buffered KR/V tiles.
// Fill of tile t+1 issues before tile t's MMA chain -> LDG latency hidden.
// 3 syncs/tile. Per-warp l (no per-tile sum exchange); halves merged at end.
// smem: Q(64*72) + 2*KR(64*72) + 2*V(64*68) + Ps(64*68) + red(256) words.
// ---------------------------------------------------------------------------
#define QST 72
#define VST 68
#define FA_Q    0
#define FA_KR0  (FA_Q  + 64 * QST)          // 4608
#define FA_KR1  (FA_KR0 + 64 * QST)         // 9216
#define FA_V0   (FA_KR1 + 64 * QST)         // 13824
#define FA_V1   (FA_V0 + 64 * VST)          // 18176
#define FA_P    (FA_V1 + 64 * VST)          // 22528
#define FA_RED  (FA_P  + 64 * VST)          // 26880
#define FA_TOT  (FA_RED + 256)              // 27136 words = 108544 B

extern __shared__ uint32_t fa_u[];

__global__ __launch_bounds__(256, 2) void flash_tf32_kernel(
    const uint32_t* __restrict__ qkv, float* __restrict__ out)
{
    uint32_t* Qs  = fa_u + FA_Q;
    uint32_t* Ps  = fa_u + FA_P;
    float* red_max = (float*)(fa_u + FA_RED);
    float* red_sum = red_max + 128;

    const int b  = blockIdx.z;
    const int h  = blockIdx.y;
    const int i0 = blockIdx.x * 64;
    const int tid  = threadIdx.x;
    const int lane = tid & 31, wid = tid >> 5;
    const int wm = wid >> 1;
    const int wn = wid & 1;
    const int lq = lane >> 2;
    const int lr = lane & 3;

    const uint32_t* qb = qkv + ((long)b * 768 + h * 64) * HW;
    const uint32_t* kb = qb + 256 * HW;
    const uint32_t* vb = qb + 512 * HW;

    // Q tile: pure bit copy
    #pragma unroll
    for (int it = 0; it < 4; it++) {
        int idx = tid + it * 256;
        int d = idx >> 4, i4 = (idx & 15) * 4;
        *(uint4*)&Qs[d * QST + i4] = *(const uint4*)&qb[(long)d * HW + i0 + i4];
    }

    const int row_lo = wm * 16 + lq;
    const int row_hi = row_lo + 8;

    float m_lo = -1e30f, m_hi = -1e30f, l_lo = 0.f, l_hi = 0.f;
    float accO[4][4];
    #pragma unroll
    for (int nt = 0; nt < 4; nt++)
        #pragma unroll
        for (int e = 0; e < 4; e++) accO[nt][e] = 0.f;

    // fill tile 0 into buffer 0
    {
        #pragma unroll
        for (int it = 0; it < 4; it++) {
            int idx = tid + it * 256;
            int d = idx >> 4, j4 = (idx & 15) * 4;
            *(uint4*)&fa_u[FA_KR0 + d * QST + j4] = *(const uint4*)&kb[(long)d * HW + j4];
            *(uint4*)&fa_u[FA_V0  + d * VST + j4] = *(const uint4*)&vb[(long)d * HW + j4];
        }
    }
    __syncthreads();

    int buf = 0;
    for (int jt = 0; jt < 16; jt++) {
        const uint32_t* KRs = fa_u + (buf ? FA_KR1 : FA_KR0);
        const uint32_t* Vs  = fa_u + (buf ? FA_V1  : FA_V0);

        // prefetch next tile into alternate buffer (no sync; visible at sync C)
        if (jt + 1 < 16) {
            uint32_t* KRn = fa_u + (buf ? FA_KR0 : FA_KR1);
            uint32_t* Vn  = fa_u + (buf ? FA_V0  : FA_V1);
            int j0n = (jt + 1) * 64;
            #pragma unroll
            for (int it = 0; it < 4; it++) {
                int idx = tid + it * 256;
                int d = idx >> 4, j4 = (idx & 15) * 4;
                *(uint4*)&KRn[d * QST + j4] = *(const uint4*)&kb[(long)d * HW + j0n + j4];
                *(uint4*)&Vn[d * VST + j4]  = *(const uint4*)&vb[(long)d * HW + j0n + j4];
            }
        }

        // S = Q^T * KR
        float s[4][4];
        #pragma unroll
        for (int nt = 0; nt < 4; nt++)
            #pragma unroll
            for (int e = 0; e < 4; e++) s[nt][e] = 0.f;

        #pragma unroll
        for (int ks = 0; ks < 8; ks++) {
            int d0 = ks * 8 + lr;
            uint32_t a0 = Qs[d0 * QST + row_lo];
            uint32_t a1 = Qs[d0 * QST + row_hi];
            uint32_t a2 = Qs[(d0 + 4) * QST + row_lo];
            uint32_t a3 = Qs[(d0 + 4) * QST + row_hi];
            #pragma unroll
            for (int nt = 0; nt < 4; nt++) {
                int jc = wn * 32 + nt * 8 + lq;
                uint32_t b0 = KRs[d0 * QST + jc];
                uint32_t b1 = KRs[(d0 + 4) * QST + jc];
                mma8(s[nt], a0, a1, a2, a3, b0, b1);
            }
        }

        #pragma unroll
        for (int nt = 0; nt < 4; nt++)
            #pragma unroll
            for (int e = 0; e < 4; e++) s[nt][e] *= 0.125f;

        // row max: quad reduce, cross-wn exchange (sync A)
        float mx_lo = -1e30f, mx_hi = -1e30f;
        #pragma unroll
        for (int nt = 0; nt < 4; nt++) {
            mx_lo = fmaxf(mx_lo, fmaxf(s[nt][0], s[nt][1]));
            mx_hi = fmaxf(mx_hi, fmaxf(s[nt][2], s[nt][3]));
        }
        mx_lo = fmaxf(mx_lo, __shfl_xor_sync(0xffffffffu, mx_lo, 1));
        mx_lo = fmaxf(mx_lo, __shfl_xor_sync(0xffffffffu, mx_lo, 2));
        mx_hi = fmaxf(mx_hi, __shfl_xor_sync(0xffffffffu, mx_hi, 1));
        mx_hi = fmaxf(mx_hi, __shfl_xor_sync(0xffffffffu, mx_hi, 2));
        if (lr == 0) {
            red_max[wn * 64 + row_lo] = mx_lo;
            red_max[wn * 64 + row_hi] = mx_hi;
        }
        __syncthreads();   // sync A
        mx_lo = fmaxf(mx_lo, red_max[(1 - wn) * 64 + row_lo]);
        mx_hi = fmaxf(mx_hi, red_max[(1 - wn) * 64 + row_hi]);

        float mn_lo = fmaxf(m_lo, mx_lo);
        float mn_hi = fmaxf(m_hi, mx_hi);
        float cr_lo = __expf(m_lo - mn_lo);
        float cr_hi = __expf(m_hi - mn_hi);
        m_lo = mn_lo; m_hi = mn_hi;

        // exp + per-warp partial row sums (no cross-warp exchange)
        float rs_lo = 0.f, rs_hi = 0.f;
        #pragma unroll
        for (int nt = 0; nt < 4; nt++) {
            float p0 = __expf(s[nt][0] - mn_lo);
            float p1 = __expf(s[nt][1] - mn_lo);
            float p2 = __expf(s[nt][2] - mn_hi);
            float p3 = __expf(s[nt][3] - mn_hi);
            rs_lo += p0 + p1;
            rs_hi += p2 + p3;
            int colb = wn * 32 + nt * 8 + 2 * lr;
            *(uint2*)&Ps[row_lo * VST + colb] = make_uint2(f2tf(p0), f2tf(p1));
            *(uint2*)&Ps[row_hi * VST + colb] = make_uint2(f2tf(p2), f2tf(p3));
        }
        rs_lo += __shfl_xor_sync(0xffffffffu, rs_lo, 1);
        rs_lo += __shfl_xor_sync(0xffffffffu, rs_lo, 2);
        rs_hi += __shfl_xor_sync(0xffffffffu, rs_hi, 1);
        rs_hi += __shfl_xor_sync(0xffffffffu, rs_hi, 2);
        l_lo = l_lo * cr_lo + rs_lo;
        l_hi = l_hi * cr_hi + rs_hi;

        __syncthreads();   // sync B: Ps ready for cross-warp PV reads

        // rescale O accumulators
        #pragma unroll
        for (int nt = 0; nt < 4; nt++) {
            accO[nt][0] *= cr_lo; accO[nt][1] *= cr_lo;
            accO[nt][2] *= cr_hi; accO[nt][3] *= cr_hi;
        }

        // O += P * V
        #pragma unroll
        for (int ks = 0; ks < 8; ks++) {
            int jj = ks * 8 + lr;
            uint32_t a0 = Ps[row_lo * VST + jj];
            uint32_t a1 = Ps[row_hi * VST + jj];
            uint32_t a2 = Ps[row_lo * VST + jj + 4];
            uint32_t a3 = Ps[row_hi * VST + jj + 4];
            #pragma unroll
            for (int nt = 0; nt < 4; nt++) {
                int dc = wn * 32 + nt * 8 + lq;
                uint32_t b0 = Vs[dc * VST + jj];
                uint32_t b1 = Vs[dc * VST + jj + 4];
                mma8(accO[nt], a0, a1, a2, a3, b0, b1);
            }
        }
        __syncthreads();   // sync C: Ps/red_max recycle + next-tile fill visible
        buf ^= 1;
    }

    // merge per-warp l halves (one exchange for the whole kernel)
    if (lr == 0) {
        red_sum[wn * 64 + row_lo] = l_lo;
        red_sum[wn * 64 + row_hi] = l_hi;
    }
    __syncthreads();
    l_lo += red_sum[(1 - wn) * 64 + row_lo];
    l_hi += red_sum[(1 - wn) * 64 + row_hi];

    float inv_lo = 1.f / l_lo;
    float inv_hi = 1.f / l_hi;
    float* ob = out + ((long)b * 256 + h * 64) * HW + i0;
    #pragma unroll
    for (int nt = 0; nt < 4; nt++) {
        int d = wn * 32 + nt * 8 + 2 * lr;
        ob[(long)d * HW + row_lo]       = accO[nt][0] * inv_lo;
        ob[(long)(d + 1) * HW + row_lo] = accO[nt][1] * inv_lo;
        ob[(long)d * HW + row_hi]       = accO[nt][2] * inv_hi;
        ob[(long)(d + 1) * HW + row_hi] = accO[nt][3] * inv_hi;
    }
}

// ---------------------------------------------------------------------------
extern "C" void kernel_launch(void* const* d_in, const int* in_sizes, int n_in,
                              void* d_out, int out_size)
{
    const float* x        = (const float*)d_in[0];
    const float* cv1_w    = (const float*)d_in[1];
    const float* cv1_bn   = (const float*)d_in[2];
    const float* cv2_w    = (const float*)d_in[3];
    const float* cv2_bn   = (const float*)d_in[4];
    const float* m_cv1_w  = (const float*)d_in[5];
    const float* m_cv1_bn = (const float*)d_in[6];
    const float* m_qkv_w  = (const float*)d_in[7];
    const float* m_rw     = (const float*)d_in[8];
    const float* m_rh     = (const float*)d_in[9];
    const float* m_cv2_w  = (const float*)d_in[10];
    const float* m_cv2_bn = (const float*)d_in[11];
    float* out = (float*)d_out;

    float *cat, *z, *qkv, *qkvp, *att, *w3, *part;
    cudaGetSymbolAddress((void**)&cat,  g_cat);
    cudaGetSymbolAddress((void**)&z,    g_z);
    cudaGetSymbolAddress((void**)&qkv,  g_qkv);
    cudaGetSymbolAddress((void**)&qkvp, g_qkvp);
    cudaGetSymbolAddress((void**)&att,  g_att);
    cudaGetSymbolAddress((void**)&w3,   g_w3);
    cudaGetSymbolAddress((void**)&part, g_part);

    const int FA_SMEM = FA_TOT * 4;   // 108544 bytes
    cudaFuncSetAttribute(flash_tf32_kernel,
                         cudaFuncAttributeMaxDynamicSharedMemorySize, FA_SMEM);

    const long CAT_S = 1024L * HW;
    const long RED_N  = (long)BATCH * 256 * HW / 4;
    const long PACK_N = (long)BATCH * 768 * HW / 4;

    reorder_w3_kernel<<<(2 * 9 * 65536 + 255) / 256, 256>>>(m_cv1_w, w3);

    // cv1: x (512) -> cat[0:512)
    gemm_tf32_kernel<<<dim3(8, 4, BATCH), 256>>>(
        x, cv1_w, cv1_bn, nullptr, cat,
        512, 512, 512L * HW, CAT_S, 0, 3);

    for (int i = 0; i < 2; i++) {
        const float* yin = cat + (long)(256 + i * 256) * HW;

        // 3x3 conv: 2-way K-split (256 blocks, single wave), then reduce
        conv3_part_kernel<<<dim3(8, 4, BATCH), 256>>>(
            yin, w3 + (long)i * 9 * 65536, part, CAT_S);
        tap_reduce_kernel<<<(int)((RED_N + 255) / 256), 256>>>(
            part, m_cv1_bn + i * 4 * 256, z);

        // qkv 1x1 (plain fp32 output)
        gemm_tf32_kernel<<<dim3(8, 6, BATCH), 256>>>(
            z, m_qkv_w + (long)i * 768 * 256, nullptr, nullptr, qkv,
            256, 768, 256L * HW, 768L * HW, 0, 0);

        // pack to tf32 bits, fold rw+rh bias into K
        qkv_pack_kernel<<<(int)((PACK_N + 255) / 256), 256>>>(
            qkv, m_rw + i * 8192, m_rh + i * 8192, qkvp);

        flash_tf32_kernel<<<dim3(16, 4, BATCH), 256, FA_SMEM>>>(
            (const uint32_t*)qkvp, att);

        gemm_tf32_kernel<<<dim3(8, 2, BATCH), 256>>>(
            att, m_cv2_w + (long)i * 256 * 256, m_cv2_bn + i * 4 * 256,
            yin, cat + (long)(512 + i * 256) * HW,
            256, 256, 256L * HW, CAT_S, CAT_S, 7);
    }

    // cv2: cat (1024) -> out (512)
    gemm_tf32_kernel<<<dim3(8, 4, BATCH), 256>>>(
        cat, cv2_w, cv2_bn, nullptr, out,
        1024, 512, CAT_S, 512L * HW, 0, 3);
}